// round 11
// baseline (speedup 1.0000x reference)
#include <cuda_runtime.h>
#include <math.h>

#define NMAX 100000
#define EMAX 1700000
#define DMAX 64
#define SCAN_CHUNK 512

// ---------------- scratch (device globals; no allocation allowed) ----------
__device__ int   g_is64;
__device__ int   g_cnt[NMAX];
__device__ int   g_off[NMAX + 1];
__device__ int   g_part[1024];
__device__ int   g_esrc[EMAX];
__device__ float g_e[EMAX];
__device__ __align__(16) float g_h[(size_t)NMAX * DMAX];
__device__ __align__(16) float g_bufA[(size_t)NMAX * DMAX];
__device__ __align__(16) float g_bufB[(size_t)NMAX * DMAX];
__device__ float g_as[NMAX];
__device__ float g_ad[NMAX];

// ---------------- dtype detection ----------------
__global__ void detect_kernel(const unsigned int* __restrict__ w) {
    if (threadIdx.x != 0 || blockIdx.x != 0) return;
    int ok64 = 1;
#pragma unroll
    for (int i = 1; i < 128; i += 2) ok64 &= (w[i] == 0u);
    g_is64 = ok64;
}

__device__ __forceinline__ int load_idx(const void* eiv, long long pos) {
    if (g_is64) return (int)((const long long*)eiv)[pos];
    return ((const int*)eiv)[pos];
}

__device__ __forceinline__ int clampN(int v, int N) {
    return (v < 0) ? 0 : (v >= N ? N - 1 : v);
}

// ---------------- CSR build ----------------
__global__ void zero_cnt_kernel(int N) {
    int i = blockIdx.x * blockDim.x + threadIdx.x;
    if (i < N) g_cnt[i] = 0;
}

__global__ void hist_kernel(const void* __restrict__ eiv, int E, int Etot, int N) {
    int i = blockIdx.x * blockDim.x + threadIdx.x;
    if (i >= Etot) return;
    int d = (i < E) ? clampN(load_idx(eiv, (long long)E + i), N) : (i - E);
    atomicAdd(&g_cnt[d], 1);
}

__global__ void scan_reduce_kernel(int N) {
    __shared__ int sh[256];
    int b = blockIdx.x, t = threadIdx.x;
    int i0 = b * SCAN_CHUNK + t * 2;
    int s = 0;
    if (i0     < N) s += g_cnt[i0];
    if (i0 + 1 < N) s += g_cnt[i0 + 1];
    sh[t] = s;
    __syncthreads();
#pragma unroll
    for (int o = 128; o; o >>= 1) {
        if (t < o) sh[t] += sh[t + o];
        __syncthreads();
    }
    if (t == 0) g_part[b] = sh[0];
}

__global__ void scan_partials_kernel(int B, int N) {
    __shared__ int sh[1024];
    int t = threadIdx.x;
    int v = (t < B) ? g_part[t] : 0;
    sh[t] = v;
    __syncthreads();
#pragma unroll
    for (int o = 1; o < 1024; o <<= 1) {
        int u = (t >= o) ? sh[t - o] : 0;
        __syncthreads();
        sh[t] += u;
        __syncthreads();
    }
    if (t < B) g_part[t] = sh[t] - v;
    if (t == 1023) g_off[N] = sh[1023];
}

__global__ void scan_final_kernel(int N) {
    __shared__ int sh[256];
    int b = blockIdx.x, t = threadIdx.x;
    int i0 = b * SCAN_CHUNK + t * 2;
    int c0 = (i0     < N) ? g_cnt[i0]     : 0;
    int c1 = (i0 + 1 < N) ? g_cnt[i0 + 1] : 0;
    int s = c0 + c1;
    sh[t] = s;
    __syncthreads();
#pragma unroll
    for (int o = 1; o < 256; o <<= 1) {
        int u = (t >= o) ? sh[t - o] : 0;
        __syncthreads();
        sh[t] += u;
        __syncthreads();
    }
    int base = g_part[b] + sh[t] - s;
    if (i0 < N)     { g_off[i0]     = base;      g_cnt[i0]     = base; }
    if (i0 + 1 < N) { g_off[i0 + 1] = base + c0; g_cnt[i0 + 1] = base + c0; }
}

__global__ void scatter_kernel(const void* __restrict__ eiv, int E, int Etot, int N) {
    int i = blockIdx.x * blockDim.x + threadIdx.x;
    if (i >= Etot) return;
    int s, d;
    if (i < E) {
        s = clampN(load_idx(eiv, i), N);
        d = clampN(load_idx(eiv, (long long)E + i), N);
    } else {
        s = d = i - E;
    }
    int p = atomicAdd(&g_cnt[d], 1);
    if (p >= 0 && p < EMAX) g_esrc[p] = s;
}

// ---------------- GEMM (128x64 tile, 8x4/thread, double-buffered) ----------
// h = X @ W  (X: [N,F], W: [F,D], D<=64, F%16==0); also g_as/g_ad = h @ a_s/a_d
__global__ __launch_bounds__(256) void gemm_kernel(
    const float* __restrict__ Xext, int sel_in,
    const float* __restrict__ W,
    const float* __restrict__ a_s, const float* __restrict__ a_d,
    int N, int F, int D, int relu_in)
{
    const float* X = (sel_in == 0) ? Xext
                   : (sel_in == 1 ? (const float*)g_bufA : (const float*)g_bufB);
    __shared__ __align__(16) float xs[2][16][132];
    __shared__ __align__(16) float ws[2][16][64];
    __shared__ float as_s[64], ad_s[64];
    int tid  = threadIdx.x;
    int row0 = blockIdx.x * 128;
    int tr = tid >> 4, tc = tid & 15;
    float acc[8][4] = {};
    int f0 = tid * 2;
    int lrow0 = f0 >> 2, lq0 = f0 & 3;
    int lrow1 = (f0 + 1) >> 2, lq1 = (f0 + 1) & 3;
    int wcol = tid & 63, wk0 = (tid >> 6) << 2;
    int gn0 = row0 + lrow0, gn1 = row0 + lrow1;
    const float4* Xr0 = reinterpret_cast<const float4*>(X + (size_t)gn0 * F);
    const float4* Xr1 = reinterpret_cast<const float4*>(X + (size_t)gn1 * F);

    if (tid < 64) {
        as_s[tid] = (tid < D) ? a_s[tid] : 0.f;
        ad_s[tid] = (tid < D) ? a_d[tid] : 0.f;
    }

    int T = F >> 4;
    float4 xv0, xv1;
    float wv[4];

    {
        xv0 = make_float4(0.f,0.f,0.f,0.f); xv1 = xv0;
        if (gn0 < N) xv0 = Xr0[lq0];
        if (gn1 < N) xv1 = Xr1[lq1];
#pragma unroll
        for (int j = 0; j < 4; j++)
            wv[j] = (wcol < D) ? W[(size_t)(wk0 + j) * D + wcol] : 0.f;
    }

    for (int t = 0; t < T; t++) {
        int cur = t & 1;
        if (relu_in) {
            xv0.x = fmaxf(xv0.x, 0.f); xv0.y = fmaxf(xv0.y, 0.f);
            xv0.z = fmaxf(xv0.z, 0.f); xv0.w = fmaxf(xv0.w, 0.f);
            xv1.x = fmaxf(xv1.x, 0.f); xv1.y = fmaxf(xv1.y, 0.f);
            xv1.z = fmaxf(xv1.z, 0.f); xv1.w = fmaxf(xv1.w, 0.f);
        }
        xs[cur][lq0 * 4 + 0][lrow0] = xv0.x;
        xs[cur][lq0 * 4 + 1][lrow0] = xv0.y;
        xs[cur][lq0 * 4 + 2][lrow0] = xv0.z;
        xs[cur][lq0 * 4 + 3][lrow0] = xv0.w;
        xs[cur][lq1 * 4 + 0][lrow1] = xv1.x;
        xs[cur][lq1 * 4 + 1][lrow1] = xv1.y;
        xs[cur][lq1 * 4 + 2][lrow1] = xv1.z;
        xs[cur][lq1 * 4 + 3][lrow1] = xv1.w;
#pragma unroll
        for (int j = 0; j < 4; j++)
            ws[cur][wk0 + j][wcol] = wv[j];
        __syncthreads();

        if (t + 1 < T) {
            int k1 = (t + 1) << 4;
            xv0 = make_float4(0.f,0.f,0.f,0.f); xv1 = xv0;
            if (gn0 < N) xv0 = Xr0[(k1 >> 2) + lq0];
            if (gn1 < N) xv1 = Xr1[(k1 >> 2) + lq1];
#pragma unroll
            for (int j = 0; j < 4; j++)
                wv[j] = (wcol < D) ? W[(size_t)(k1 + wk0 + j) * D + wcol] : 0.f;
        }

#pragma unroll
        for (int k = 0; k < 16; k++) {
            float4 a04 = *(const float4*)&xs[cur][k][tr * 8];
            float4 a48 = *(const float4*)&xs[cur][k][tr * 8 + 4];
            float4 b   = *(const float4*)&ws[cur][k][tc * 4];
            acc[0][0] += a04.x * b.x; acc[0][1] += a04.x * b.y; acc[0][2] += a04.x * b.z; acc[0][3] += a04.x * b.w;
            acc[1][0] += a04.y * b.x; acc[1][1] += a04.y * b.y; acc[1][2] += a04.y * b.z; acc[1][3] += a04.y * b.w;
            acc[2][0] += a04.z * b.x; acc[2][1] += a04.z * b.y; acc[2][2] += a04.z * b.z; acc[2][3] += a04.z * b.w;
            acc[3][0] += a04.w * b.x; acc[3][1] += a04.w * b.y; acc[3][2] += a04.w * b.z; acc[3][3] += a04.w * b.w;
            acc[4][0] += a48.x * b.x; acc[4][1] += a48.x * b.y; acc[4][2] += a48.x * b.z; acc[4][3] += a48.x * b.w;
            acc[5][0] += a48.y * b.x; acc[5][1] += a48.y * b.y; acc[5][2] += a48.y * b.z; acc[5][3] += a48.y * b.w;
            acc[6][0] += a48.z * b.x; acc[6][1] += a48.z * b.y; acc[6][2] += a48.z * b.z; acc[6][3] += a48.z * b.w;
            acc[7][0] += a48.w * b.x; acc[7][1] += a48.w * b.y; acc[7][2] += a48.w * b.z; acc[7][3] += a48.w * b.w;
        }
        __syncthreads();
    }

    float sdot[8] = {}, ddot[8] = {};
    int c0 = tc * 4;
#pragma unroll
    for (int i = 0; i < 8; i++) {
        int n = row0 + tr * 8 + i;
        bool ok = (n < N);
#pragma unroll
        for (int j = 0; j < 4; j++) {
            int c = c0 + j;
            if (ok && c < D) g_h[(size_t)n * D + c] = acc[i][j];
            float w = (c < D) ? acc[i][j] : 0.f;
            sdot[i] += w * as_s[c];
            ddot[i] += w * ad_s[c];
        }
    }
#pragma unroll
    for (int o = 8; o; o >>= 1) {
#pragma unroll
        for (int i = 0; i < 8; i++) {
            sdot[i] += __shfl_xor_sync(0xffffffffu, sdot[i], o);
            ddot[i] += __shfl_xor_sync(0xffffffffu, ddot[i], o);
        }
    }
    if (tc == 0) {
#pragma unroll
        for (int i = 0; i < 8; i++) {
            int n = row0 + tr * 8 + i;
            if (n < N) { g_as[n] = sdot[i]; g_ad[n] = ddot[i]; }
        }
    }
}

// ---------------- fused segment softmax + aggregation (warp per dst) -------
// pass 3 uses quarter-warp edge parallelism: 4 quads of 8 lanes, each quad
// handles every 4th edge; each lane covers 8 columns (2x LDG.128).
__global__ void agg_kernel(float* OUText, int sel_out, int N, int D)
{
    float* OUT = (sel_out == 0) ? OUText : (sel_out == 1 ? g_bufA : g_bufB);
    int warp = (blockIdx.x * blockDim.x + threadIdx.x) >> 5;
    int lane = threadIdx.x & 31;
    int nw = (gridDim.x * blockDim.x) >> 5;
    const float4* H4 = reinterpret_cast<const float4*>(g_h);
    int rowst = D >> 2;
    int quad = lane >> 3;          // 0..3
    int ql   = lane & 7;           // lane within quad
    int c0   = ql * 8;
    bool act = (c0 < D);           // D % 8 == 0 for both 64 and 40
    int rq   = ql * 2;             // float4 index within row

    for (int n = warp; n < N; n += nw) {
        int beg = g_off[n], end = g_off[n + 1];
        float adn = g_ad[n];

        // pass 1: ex = exp(leaky_relu(as[src]+ad[n])), cache + sum
        float sum = 0.f;
        for (int p = beg + lane; p < end; p += 32) {
            float v = g_as[g_esrc[p]] + adn;
            v = (v > 0.f) ? v : 0.2f * v;
            float ex = __expf(v);
            g_e[p] = ex;
            sum += ex;
        }
#pragma unroll
        for (int o = 16; o; o >>= 1) sum += __shfl_xor_sync(0xffffffffu, sum, o);
        float inv = 1.f / (sum + 1e-16f);

        // pass 3: each quad handles every 4th edge; lane covers 8 cols
        float4 accA = make_float4(0.f, 0.f, 0.f, 0.f);
        float4 accB = make_float4(0.f, 0.f, 0.f, 0.f);
#pragma unroll 2
        for (int p = beg + quad; p < end; p += 4) {
            float a = g_e[p] * inv;     // broadcast within quad
            int s = g_esrc[p];
            if (act) {
                float4 hA = H4[(size_t)s * rowst + rq];
                float4 hB = H4[(size_t)s * rowst + rq + 1];
                accA.x += a * hA.x; accA.y += a * hA.y;
                accA.z += a * hA.z; accA.w += a * hA.w;
                accB.x += a * hB.x; accB.y += a * hB.y;
                accB.z += a * hB.z; accB.w += a * hB.w;
            }
        }
        // combine the 4 quads (same columns, different edge subsets)
#pragma unroll
        for (int o = 8; o <= 16; o <<= 1) {
            accA.x += __shfl_xor_sync(0xffffffffu, accA.x, o);
            accA.y += __shfl_xor_sync(0xffffffffu, accA.y, o);
            accA.z += __shfl_xor_sync(0xffffffffu, accA.z, o);
            accA.w += __shfl_xor_sync(0xffffffffu, accA.w, o);
            accB.x += __shfl_xor_sync(0xffffffffu, accB.x, o);
            accB.y += __shfl_xor_sync(0xffffffffu, accB.y, o);
            accB.z += __shfl_xor_sync(0xffffffffu, accB.z, o);
            accB.w += __shfl_xor_sync(0xffffffffu, accB.w, o);
        }
        if (quad == 0 && act) {
            *reinterpret_cast<float4*>(&OUT[(size_t)n * D + c0])     = accA;
            *reinterpret_cast<float4*>(&OUT[(size_t)n * D + c0 + 4]) = accB;
        }
    }
}

// ---------------- launch ----------------
extern "C" void kernel_launch(void* const* d_in, const int* in_sizes, int n_in,
                              void* d_out, int out_size)
{
    const float* x     = (const float*)d_in[0];
    const void*  ei    = d_in[1];
    const float* W0    = (const float*)d_in[2];
    const float* asrc0 = (const float*)d_in[3];
    const float* adst0 = (const float*)d_in[4];
    const float* W1    = (const float*)d_in[5];
    const float* asrc1 = (const float*)d_in[6];
    const float* adst1 = (const float*)d_in[7];
    const float* W2    = (const float*)d_in[8];
    const float* asrc2 = (const float*)d_in[9];
    const float* adst2 = (const float*)d_in[10];

    int H    = in_sizes[3];            // 64
    int C    = in_sizes[9];            // 40
    int Fin  = in_sizes[2] / H;        // 256
    int N    = in_sizes[0] / Fin;      // 100000
    int E    = in_sizes[1] / 2;        // 1600000
    int Etot = E + N;
    int SB   = (N + SCAN_CHUNK - 1) / SCAN_CHUNK;

    static cudaStream_t s2 = nullptr;
    static cudaEvent_t ev_fork = nullptr, ev_csr = nullptr;
    if (!s2) {
        cudaStreamCreateWithFlags(&s2, cudaStreamNonBlocking);
        cudaEventCreateWithFlags(&ev_fork, cudaEventDisableTiming);
        cudaEventCreateWithFlags(&ev_csr, cudaEventDisableTiming);
    }

    int gemm_blocks = (N + 127) / 128;
    int wg_blocks   = (N + 7) / 8;

    // fork: CSR build on s2, concurrent with gemm0 on the main stream
    cudaEventRecord(ev_fork, 0);
    cudaStreamWaitEvent(s2, ev_fork, 0);

    detect_kernel<<<1, 32, 0, s2>>>((const unsigned int*)ei);
    zero_cnt_kernel<<<(N + 255) / 256, 256, 0, s2>>>(N);
    hist_kernel<<<(Etot + 255) / 256, 256, 0, s2>>>(ei, E, Etot, N);
    scan_reduce_kernel<<<SB, 256, 0, s2>>>(N);
    scan_partials_kernel<<<1, 1024, 0, s2>>>(SB, N);
    scan_final_kernel<<<SB, 256, 0, s2>>>(N);
    scatter_kernel<<<(Etot + 255) / 256, 256, 0, s2>>>(ei, E, Etot, N);
    cudaEventRecord(ev_csr, s2);

    // layer 0 GEMM (concurrent with CSR build)
    gemm_kernel<<<gemm_blocks, 256>>>(x, 0, W0, asrc0, adst0, N, Fin, H, 0);

    cudaStreamWaitEvent(0, ev_csr, 0);
    agg_kernel<<<wg_blocks, 256>>>(nullptr, 1, N, H);

    gemm_kernel<<<gemm_blocks, 256>>>(nullptr, 1, W1, asrc1, adst1, N, H, H, 1);
    agg_kernel<<<wg_blocks, 256>>>(nullptr, 2, N, H);

    gemm_kernel<<<gemm_blocks, 256>>>(nullptr, 2, W2, asrc2, adst2, N, H, C, 1);
    agg_kernel<<<wg_blocks, 256>>>((float*)d_out, 0, N, C);
}